// round 15
// baseline (speedup 1.0000x reference)
#include <cuda_runtime.h>
#include <cstdint>
#include <math.h>

#define BB 8
#define NN 4096
#define CINC 64
#define COUTC 128
#define SS 1024
#define NSK 32
#define VV 4
#define H1C 64
#define H2C 128

// ---------------- scratch (device globals; no runtime allocation) ----------
__device__ int    g_new_idx[BB*SS];
__device__ int    g_gidx[BB*SS*NSK];
__device__ double g_bsum[BB], g_bsq[BB];
__device__ float  g_std[BB];
__device__ double g_s1[H1C], g_q1[H1C];
__device__ float  g_sc1[H1C], g_sh1[H1C];
__device__ double g_s2[H2C], g_q2[H2C];
__device__ float  g_sc2[H2C], g_sh2[H2C];
__device__ float  g_skip[(size_t)BB*SS*NSK*CINC];   // 64 MB
__device__ float  g_h2v[(size_t)BB*SS*NSK*H2C];     // 128 MB
__device__ float  g_mixwt[134*64];
__device__ float  g_m1w2t[64*64];
__device__ float  g_m2w1t[64*128];
__device__ float  g_m2w2t[128*128];
__device__ float  g_reswt[64*128];

// ---------------- helpers ---------------------------------------------------
__device__ __forceinline__ float gelu_exact(float x){
    return 0.5f * x * (1.0f + erff(x * 0.70710678118654752440f));
}

__device__ __forceinline__ uint32_t rotl32(uint32_t x, int r){
    return (x << r) | (x >> (32 - r));
}

// Distance computed exactly as XLA lowers jnp.sum((a-b)**2, -1):
// un-fused sub/mul, left-to-right add. No FMA contraction allowed here —
// FPS argmax and ball-query membership are discrete decisions.
__device__ __forceinline__ float d2_exact(float ax, float ay, float az,
                                          float bx, float by, float bz){
    float dx = __fsub_rn(ax, bx);
    float dy = __fsub_rn(ay, by);
    float dz = __fsub_rn(az, bz);
    float sx = __fmul_rn(dx, dx);
    float sy = __fmul_rn(dy, dy);
    float sz = __fmul_rn(dz, dz);
    return __fadd_rn(__fadd_rn(sx, sy), sz);
}

// JAX *partitionable* threefry (default since jax 0.4.36), key = (0, 42).
// Per-element 64-bit counter = flat row-major index i (< 2^32 here), fed as
// (counts_hi, counts_lo) = (0, i). 32-bit output = x0_final ^ x1_final.
__device__ __forceinline__ uint32_t threefry_bits(uint32_t i){
    const uint32_t k0 = 0u, k1 = 42u;
    const uint32_t k2 = 0x1BD11BDAu ^ k0 ^ k1;
    uint32_t x0 = 0u + k0;      // counts_hi + ks[0]
    uint32_t x1 = i  + k1;      // counts_lo + ks[1]
#define TFR(r) { x0 += x1; x1 = rotl32(x1, r); x1 ^= x0; }
    TFR(13) TFR(15) TFR(26) TFR(6)
    x0 += k1; x1 += k2 + 1u;
    TFR(17) TFR(29) TFR(16) TFR(24)
    x0 += k2; x1 += k0 + 2u;
    TFR(13) TFR(15) TFR(26) TFR(6)
    x0 += k0; x1 += k1 + 3u;
    TFR(17) TFR(29) TFR(16) TFR(24)
    x0 += k1; x1 += k2 + 4u;
    TFR(13) TFR(15) TFR(26) TFR(6)
    x0 += k2; x1 += k0 + 5u;
#undef TFR
    return x0 ^ x1;
}

__device__ __forceinline__ float gumbel_at(uint32_t i){
    uint32_t bits = threefry_bits(i);
    float u = __uint_as_float((bits >> 9) | 0x3F800000u) - 1.0f;   // [0,1)
    // maxval-minval = 1.0f - 1e-9f rounds to exactly 1.0f in fp32
    float r = __fadd_rn(u, 1e-9f);
    r = fmaxf(1e-9f, r);
    return -logf(-logf(r));
}

// ---------------- init ------------------------------------------------------
__global__ void k_init(){
    int t = threadIdx.x;
    if (t < BB) { g_bsum[t] = 0.0; g_bsq[t] = 0.0; }
    if (t < H1C){ g_s1[t] = 0.0;  g_q1[t] = 0.0; }
    if (t < H2C){ g_s2[t] = 0.0;  g_q2[t] = 0.0; }
}

// ---------------- transpose weights into [c][o] layout ----------------------
__global__ void k_prep(const float* __restrict__ mixw, const float* __restrict__ m1w2,
                       const float* __restrict__ m2w1, const float* __restrict__ m2w2,
                       const float* __restrict__ resw){
    int i = blockIdx.x * blockDim.x + threadIdx.x;   // up to 16384
    if (i < 134*64)  g_mixwt[i] = mixw[(i & 63) * 134 + (i >> 6)];
    if (i < 64*64)   g_m1w2t[i] = m1w2[(i & 63) * 64  + (i >> 6)];
    if (i < 64*128)  g_m2w1t[i] = m2w1[(i & 127) * 64 + (i >> 7)];
    if (i < 128*128) g_m2w2t[i] = m2w2[(i & 127) * 128 + (i >> 7)];
    if (i < 64*128)  g_reswt[i] = resw[(i & 127) * 64 + (i >> 7)];
}

// ---------------- farthest point sampling -----------------------------------
__global__ void k_fps(const float* __restrict__ xyz, float* __restrict__ out_nx){
    int b = blockIdx.x;
    const float* X = xyz + (size_t)b * NN * 3;
    int t = threadIdx.x;
    int lane = t & 31, warp = t >> 5;

    float px[4], py[4], pz[4], mind[4];
    const float FINF = __int_as_float(0x7f800000);
#pragma unroll
    for (int k = 0; k < 4; k++){
        int j = t + k * 1024;
        px[k] = X[j*3]; py[k] = X[j*3+1]; pz[k] = X[j*3+2];
        mind[k] = FINF;
    }
    __shared__ float s_v[32];
    __shared__ int   s_i[32];
    __shared__ int   s_last;

    if (t == 0){
        g_new_idx[b*SS] = 0;
        out_nx[(size_t)(b*SS)*3+0] = X[0];
        out_nx[(size_t)(b*SS)*3+1] = X[1];
        out_nx[(size_t)(b*SS)*3+2] = X[2];
    }
    int last = 0;
    for (int it = 1; it < SS; ++it){
        float qx = X[last*3], qy = X[last*3+1], qz = X[last*3+2];
        float bv = -1.0f; int bi = 0x7fffffff;
#pragma unroll
        for (int k = 0; k < 4; k++){
            float d = d2_exact(px[k], py[k], pz[k], qx, qy, qz);
            float m = fminf(mind[k], d);
            mind[k] = m;
            int j = t + k * 1024;
            if (m > bv || (m == bv && j < bi)) { bv = m; bi = j; }
        }
#pragma unroll
        for (int off = 16; off > 0; off >>= 1){
            float ov = __shfl_down_sync(0xffffffffu, bv, off);
            int   oi = __shfl_down_sync(0xffffffffu, bi, off);
            if (ov > bv || (ov == bv && oi < bi)) { bv = ov; bi = oi; }
        }
        if (lane == 0){ s_v[warp] = bv; s_i[warp] = bi; }
        __syncthreads();
        if (warp == 0){
            bv = s_v[lane]; bi = s_i[lane];
#pragma unroll
            for (int off = 16; off > 0; off >>= 1){
                float ov = __shfl_down_sync(0xffffffffu, bv, off);
                int   oi = __shfl_down_sync(0xffffffffu, bi, off);
                if (ov > bv || (ov == bv && oi < bi)) { bv = ov; bi = oi; }
            }
            if (lane == 0){
                s_last = bi;
                g_new_idx[b*SS + it] = bi;
                out_nx[(size_t)(b*SS+it)*3+0] = X[bi*3];
                out_nx[(size_t)(b*SS+it)*3+1] = X[bi*3+1];
                out_nx[(size_t)(b*SS+it)*3+2] = X[bi*3+2];
            }
        }
        __syncthreads();
        last = s_last;
    }
}

// ---------------- ball query ------------------------------------------------
__global__ void k_ballq(const float* __restrict__ xyz, const float* __restrict__ nx){
    extern __shared__ float sx[];   // NN*3 floats = 48 KB
    int b = blockIdx.x >> 7;
    int t = threadIdx.x;
    int warp = t >> 5, lane = t & 31;
    const float* X = xyz + (size_t)b * NN * 3;
    for (int i = t; i < NN*3; i += 256) sx[i] = X[i];
    __syncthreads();

    int s = ((blockIdx.x & 127) << 3) + warp;
    int bs = b * SS + s;
    float cx = nx[(size_t)bs*3], cy = nx[(size_t)bs*3+1], cz = nx[(size_t)bs*3+2];
    // f32(0.2*0.2 computed in double) = 0x3D23D70A; NOT 0.2f*0.2f (1 ulp larger)
    const float r2 = 0.04f;
    int cnt = 0;
    int* G = g_gidx + (size_t)bs * NSK;
    for (int base = 0; base < NN; base += 32){
        int j = base + lane;
        float d2 = d2_exact(cx, cy, cz, sx[j*3], sx[j*3+1], sx[j*3+2]);
        bool w = d2 < r2;
        unsigned m = __ballot_sync(0xffffffffu, w);
        int off = __popc(m & ((1u << lane) - 1u));
        if (w && (cnt + off) < NSK) G[cnt + off] = j;
        cnt += __popc(m);
        if (cnt >= NSK) break;
    }
    if (cnt < NSK){
        for (int q = cnt + lane; q < NSK; q += 32) G[q] = -1;
    }
}

// ---------------- per-batch std of gf ----------------------------------------
__global__ void k_std(const float* __restrict__ xyz, const float* __restrict__ f,
                      const float* __restrict__ nx){
    int t = threadIdx.x;
    int row = blockIdx.x * 256 + t;        // 0 .. 262143
    int b  = row >> 15;
    int bs = row >> 5;
    int gi = g_gidx[row];
    int si = g_new_idx[bs];
    const float* Fs = f + ((size_t)b*NN + si) * CINC;
    float cx = nx[(size_t)bs*3], cy = nx[(size_t)bs*3+1], cz = nx[(size_t)bs*3+2];
    float gx = 0.f, gy = 0.f, gz = 0.f;
    const float* Fg = f;  // dummy
    if (gi >= 0){
        const float* P = xyz + ((size_t)b*NN + gi)*3;
        gx = P[0]; gy = P[1]; gz = P[2];
        Fg = f + ((size_t)b*NN + gi) * CINC;
    }
    double ls = 0.0, lq = 0.0;
    float v;
    v = gx;      ls += v; lq += (double)v*v;
    v = gy;      ls += v; lq += (double)v*v;
    v = gz;      ls += v; lq += (double)v*v;
    v = gx - cx; ls += v; lq += (double)v*v;
    v = gy - cy; ls += v; lq += (double)v*v;
    v = gz - cz; ls += v; lq += (double)v*v;
    for (int c = 0; c < CINC; c++){
        float fv = (gi >= 0) ? Fg[c] : 0.0f;
        v = fv - Fs[c]; ls += v; lq += (double)v*v;
    }
    __shared__ double sd[256];
    sd[t] = ls; __syncthreads();
    for (int o = 128; o > 0; o >>= 1){ if (t < o) sd[t] += sd[t+o]; __syncthreads(); }
    if (t == 0) atomicAdd(&g_bsum[b], sd[0]);
    __syncthreads();
    sd[t] = lq; __syncthreads();
    for (int o = 128; o > 0; o >>= 1){ if (t < o) sd[t] += sd[t+o]; __syncthreads(); }
    if (t == 0) atomicAdd(&g_bsq[b], sd[0]);
}

__global__ void k_stdfin(){
    int b = threadIdx.x;
    if (b < BB){
        double cnt = (double)SS * NSK * (CINC + 6);
        double s = g_bsum[b], q = g_bsq[b];
        double mean = s / cnt;
        double var = (q - s * mean) / (cnt - 1.0);
        g_std[b] = (float)sqrt(var);
    }
}

// ---------------- grouped_f (= group_skip) ----------------------------------
__global__ void k_groupedf(const float* __restrict__ xyz, const float* __restrict__ f,
                           const float* __restrict__ aw, const float* __restrict__ ab,
                           const float* __restrict__ mixb, const float* __restrict__ nx){
    __shared__ float s_w[134*64];
    __shared__ float s_gf[134];
    __shared__ float s_samp[CINC];
    __shared__ float s_aw[70], s_ab[70];
    int bs = blockIdx.x; int b = bs >> 10;
    int t = threadIdx.x;   // 64
    for (int i = t; i < 134*64; i += 64) s_w[i] = g_mixwt[i];
    int si = g_new_idx[bs];
    s_samp[t] = f[((size_t)b*NN + si)*CINC + t];
    for (int i = t; i < 70; i += 64){ s_aw[i] = aw[i]; s_ab[i] = ab[i]; }
    float cx = nx[(size_t)bs*3], cy = nx[(size_t)bs*3+1], cz = nx[(size_t)bs*3+2];
    float stdp = g_std[b] + 1e-5f;
    float mb = mixb[t];
    __syncthreads();
    for (int n = 0; n < NSK; n++){
        int row = bs * NSK + n;
        int gi = g_gidx[row];
        for (int c = t; c < 134; c += 64){
            float val;
            if (c < 70){
                float raw;
                if (c < 3){
                    raw = (gi >= 0) ? xyz[((size_t)b*NN+gi)*3 + c] : 0.0f;
                } else if (c < 6){
                    float g = (gi >= 0) ? xyz[((size_t)b*NN+gi)*3 + (c-3)] : 0.0f;
                    float cen = (c == 3) ? cx : (c == 4) ? cy : cz;
                    raw = g - cen;
                } else {
                    float g = (gi >= 0) ? f[((size_t)b*NN+gi)*CINC + (c-6)] : 0.0f;
                    raw = g - s_samp[c-6];
                }
                val = (raw / stdp) * s_aw[c] + s_ab[c];
            } else {
                val = s_samp[c-70];
            }
            s_gf[c] = val;
        }
        __syncthreads();
        float acc = mb;
#pragma unroll 2
        for (int c = 0; c < 134; c++) acc += s_gf[c] * s_w[c*64 + t];
        g_skip[(size_t)row*CINC + t] = acc;
        __syncthreads();
    }
}

// ---------------- BN1 statistics (recompute h) -------------------------------
__global__ void k_bn1(const float* __restrict__ xyz, const int* __restrict__ cidx,
                      const float* __restrict__ w1, const float* __restrict__ b1){
    int t = threadIdx.x;   // 64 = channel
    int row0 = blockIdx.x * 256;
    int b = row0 >> 15;
    __shared__ float s_mc[12];
    if (t < 12){
        int v = t / 3, k = t % 3;
        s_mc[t] = xyz[((size_t)b*NN + cidx[v])*3 + k];
    }
    float w[13];
#pragma unroll
    for (int c = 0; c < 13; c++) w[c] = w1[t*13 + c];
    float bb = b1[t];
    __syncthreads();
    double ls = 0.0, lq = 0.0;
    for (int r = 0; r < 256; r++){
        int row = row0 + r;
        int gi = g_gidx[row];
        float gx = 0.f, gy = 0.f, gz = 0.f;
        if (gi >= 0){
            const float* P = xyz + ((size_t)b*NN + gi)*3;
            gx = P[0]; gy = P[1]; gz = P[2];
        }
#pragma unroll
        for (int v = 0; v < VV; v++){
            float mx = s_mc[v*3], my = s_mc[v*3+1], mz = s_mc[v*3+2];
            float ax = gx - mx, ay = gy - my, az = gz - mz;
            float eu = sqrtf(ax*ax + ay*ay + az*az);
            float h = bb - w[0]*ax - w[1]*ay - w[2]*az
                         + w[3]*ax + w[4]*ay + w[5]*az
                         + w[6]*eu + w[7]*gx + w[8]*gy + w[9]*gz
                         + w[10]*mx + w[11]*my + w[12]*mz;
            ls += h; lq += (double)h*h;
        }
    }
    atomicAdd(&g_s1[t], ls);
    atomicAdd(&g_q1[t], lq);
}

__global__ void k_bn1fin(const float* __restrict__ g1, const float* __restrict__ be1){
    int t = threadIdx.x;
    if (t < H1C){
        double cnt = (double)BB * SS * NSK * VV;
        double mean = g_s1[t] / cnt;
        double var  = g_q1[t] / cnt - mean * mean;
        float sc = g1[t] / sqrtf((float)var + 1e-5f);
        g_sc1[t] = sc;
        g_sh1[t] = be1[t] - (float)mean * sc;
    }
}

// ---------------- main fused kernel ------------------------------------------
__global__ void k_main(const float* __restrict__ xyz, const int* __restrict__ cidx,
                       const float* __restrict__ w1, const float* __restrict__ b1,
                       const float* __restrict__ m1b2, const float* __restrict__ m2b1){
    extern __shared__ float sm[];
    float* s_w2  = sm;             // 4096  : m1_w2^T  [c*64+o]
    float* s_mw1 = sm + 4096;      // 8192  : m2_w1^T  [c*128+o]
    float* s_h   = sm + 12288;     // 256   : h (v,64)
    float* s_agg = sm + 12544;     // 64
    float* s_mc  = sm + 12608;     // 12
    int bs = blockIdx.x; int b = bs >> 10;
    int t = threadIdx.x;   // 64

    for (int i = t; i < 4096; i += 64) s_w2[i]  = g_m1w2t[i];
    for (int i = t; i < 8192; i += 64) s_mw1[i] = g_m2w1t[i];
    if (t < 12){ int v = t/3, k = t%3; s_mc[t] = xyz[((size_t)b*NN + cidx[v])*3 + k]; }
    float w[13];
#pragma unroll
    for (int c = 0; c < 13; c++) w[c] = w1[t*13 + c];
    float bb = b1[t], sc1 = g_sc1[t], sh1 = g_sh1[t], b2 = m1b2[t];
    float mb1a = m2b1[t], mb1b = m2b1[t + 64];
    double s2a = 0, q2a = 0, s2b = 0, q2b = 0;
    __syncthreads();

    for (int n = 0; n < NSK; n++){
        int row = bs * NSK + n;
        int gi = g_gidx[row];
        float gx = 0.f, gy = 0.f, gz = 0.f;
        if (gi >= 0){
            const float* P = xyz + ((size_t)b*NN + gi)*3;
            gx = P[0]; gy = P[1]; gz = P[2];
        }
#pragma unroll
        for (int v = 0; v < VV; v++){
            float mx = s_mc[v*3], my = s_mc[v*3+1], mz = s_mc[v*3+2];
            float ax = gx - mx, ay = gy - my, az = gz - mz;
            float eu = sqrtf(ax*ax + ay*ay + az*az);
            float h = bb - w[0]*ax - w[1]*ay - w[2]*az
                         + w[3]*ax + w[4]*ay + w[5]*az
                         + w[6]*eu + w[7]*gx + w[8]*gy + w[9]*gz
                         + w[10]*mx + w[11]*my + w[12]*mz;
            h = h * sc1 + sh1;
            s_h[v*64 + t] = gelu_exact(h);
        }
        __syncthreads();

        float skip = g_skip[(size_t)row*CINC + t];
        float lo[VV], zz[VV];
#pragma unroll
        for (int v = 0; v < VV; v++){
            float acc = b2;
#pragma unroll 8
            for (int c = 0; c < 64; c++) acc += s_h[v*64 + c] * s_w2[c*64 + t];
            lo[v] = skip * acc;
            uint32_t fi = ((uint32_t)row * VV + (uint32_t)v) * 64u + (uint32_t)t;
            zz[v] = lo[v] + gumbel_at(fi);
        }
        float m = fmaxf(fmaxf(zz[0], zz[1]), fmaxf(zz[2], zz[3]));
        float se = 0.f, sl = 0.f;
#pragma unroll
        for (int v = 0; v < VV; v++){
            float e = expf(zz[v] - m);
            se += e; sl += e * lo[v];
        }
        float agg = sl / se + skip;
        if (gi < 0) agg = 0.0f;
        s_agg[t] = agg;
        __syncthreads();

        float ha = mb1a, hb = mb1b;
#pragma unroll 8
        for (int c = 0; c < 64; c++){
            float a = s_agg[c];
            ha += a * s_mw1[c*128 + t];
            hb += a * s_mw1[c*128 + t + 64];
        }
        g_h2v[(size_t)row*H2C + t]      = ha;
        g_h2v[(size_t)row*H2C + t + 64] = hb;
        s2a += ha; q2a += (double)ha*ha;
        s2b += hb; q2b += (double)hb*hb;
        __syncthreads();
    }
    atomicAdd(&g_s2[t],      s2a); atomicAdd(&g_q2[t],      q2a);
    atomicAdd(&g_s2[t + 64], s2b); atomicAdd(&g_q2[t + 64], q2b);
}

__global__ void k_bn2fin(const float* __restrict__ g2, const float* __restrict__ be2){
    int t = threadIdx.x;
    if (t < H2C){
        double cnt = (double)BB * SS * NSK;
        double mean = g_s2[t] / cnt;
        double var  = g_q2[t] / cnt - mean * mean;
        float sc = g2[t] / sqrtf((float)var + 1e-5f);
        g_sc2[t] = sc;
        g_sh2[t] = be2[t] - (float)mean * sc;
    }
}

// ---------------- final kernel ------------------------------------------------
__global__ void k_final(const float* __restrict__ m2b2, const float* __restrict__ resb,
                        float* __restrict__ out_f){
    extern __shared__ float sm[];
    float* s_w = sm;            // 16384 : m2_w2^T [c*128+o]
    float* s_r = sm + 16384;    // 8192  : res_w^T [c*128+o]
    float* s_h = sm + 24576;    // 128
    float* s_k = sm + 24704;    // 64
    int bs = blockIdx.x;
    int t = threadIdx.x;   // 128
    for (int i = t; i < 16384; i += 128) s_w[i] = g_m2w2t[i];
    for (int i = t; i < 8192;  i += 128) s_r[i] = g_reswt[i];
    float ob = m2b2[t], rb = resb[t];
    float sc2 = g_sc2[t], sh2 = g_sh2[t];
    __syncthreads();
    float mx = -3.4e38f;
    for (int n = 0; n < NSK; n++){
        int row = bs * NSK + n;
        s_h[t] = g_h2v[(size_t)row*H2C + t] * sc2 + sh2;
        if (t < 64) s_k[t] = g_skip[(size_t)row*CINC + t];
        __syncthreads();
        float acc = ob;
#pragma unroll 8
        for (int c = 0; c < 128; c++) acc += s_h[c] * s_w[c*128 + t];
        float r = rb;
#pragma unroll 8
        for (int c = 0; c < 64; c++)  r += s_k[c] * s_r[c*128 + t];
        float v = gelu_exact(acc + r);
        mx = fmaxf(mx, v);
        __syncthreads();
    }
    out_f[(size_t)bs*COUTC + t] = mx;
}

// ---------------- launch -----------------------------------------------------
extern "C" void kernel_launch(void* const* d_in, const int* in_sizes, int n_in,
                              void* d_out, int out_size){
    const float* xyz   = (const float*)d_in[0];
    const float* f     = (const float*)d_in[1];
    const int*   cidx  = (const int*)  d_in[2];
    const float* aw    = (const float*)d_in[3];
    const float* ab    = (const float*)d_in[4];
    const float* mixw  = (const float*)d_in[5];
    const float* mixb  = (const float*)d_in[6];
    const float* m1w1  = (const float*)d_in[7];
    const float* m1b1  = (const float*)d_in[8];
    const float* m1g1  = (const float*)d_in[9];
    const float* m1be1 = (const float*)d_in[10];
    const float* m1w2  = (const float*)d_in[11];
    const float* m1b2  = (const float*)d_in[12];
    const float* m2w1  = (const float*)d_in[13];
    const float* m2b1  = (const float*)d_in[14];
    const float* m2g1  = (const float*)d_in[15];
    const float* m2be1 = (const float*)d_in[16];
    const float* m2w2  = (const float*)d_in[17];
    const float* m2b2  = (const float*)d_in[18];
    const float* resw  = (const float*)d_in[19];
    const float* resb  = (const float*)d_in[20];
    (void)in_sizes; (void)n_in; (void)out_size; (void)m1w2; (void)mixw;

    float* outf = (float*)d_out;                       // (B,S,COUT)
    float* outx = outf + (size_t)BB*SS*COUTC;          // (B,S,3)

    cudaFuncSetAttribute(k_ballq, cudaFuncAttributeMaxDynamicSharedMemorySize, 49152);
    cudaFuncSetAttribute(k_main,  cudaFuncAttributeMaxDynamicSharedMemorySize, 51200);
    cudaFuncSetAttribute(k_final, cudaFuncAttributeMaxDynamicSharedMemorySize, 100352);

    k_init<<<1, 128>>>();
    k_prep<<<64, 256>>>(mixw, m1w2, m2w1, m2w2, resw);
    k_fps<<<BB, 1024>>>(xyz, outx);
    k_ballq<<<BB*SS/8, 256, 49152>>>(xyz, outx);
    k_std<<<(BB*SS*NSK)/256, 256>>>(xyz, f, outx);
    k_stdfin<<<1, 32>>>();
    k_groupedf<<<BB*SS, 64>>>(xyz, f, aw, ab, mixb, outx);
    k_bn1<<<1024, 64>>>(xyz, cidx, m1w1, m1b1);
    k_bn1fin<<<1, 64>>>(m1g1, m1be1);
    k_main<<<BB*SS, 64, 50480>>>(xyz, cidx, m1w1, m1b1, m1b2, m2b1);
    k_bn2fin<<<1, 128>>>(m2g1, m2be1);
    k_final<<<BB*SS, 128, 99072>>>(m2b2, resb, outf);
}

// round 16
// speedup vs baseline: 1.5622x; 1.5622x over previous
#include <cuda_runtime.h>
#include <cstdint>
#include <math.h>

#define BB 8
#define NN 4096
#define CINC 64
#define COUTC 128
#define SS 1024
#define NSK 32
#define VV 4
#define H1C 64
#define H2C 128

// ---------------- scratch (device globals; no runtime allocation) ----------
__device__ int    g_new_idx[BB*SS];
__device__ int    g_gidx[BB*SS*NSK];
__device__ double g_bsum[BB], g_bsq[BB];
__device__ float  g_std[BB];
__device__ double g_s1[H1C], g_q1[H1C];
__device__ float  g_sc1[H1C], g_sh1[H1C];
__device__ double g_s2[H2C], g_q2[H2C];
__device__ float  g_sc2[H2C], g_sh2[H2C];
__device__ float  g_skip[(size_t)BB*SS*NSK*CINC];   // 64 MB
__device__ float  g_h2v[(size_t)BB*SS*NSK*H2C];     // 128 MB
__device__ float  g_mixwt[134*64];
__device__ float  g_m1w2t[64*64];
__device__ float  g_m2w1p[64*128];    // paired: [cc][c][2] = m2w1[(c+64*h)][cc]
__device__ float  g_m2w2t[128*128];
__device__ float  g_reswt[64*128];

// ---------------- helpers ---------------------------------------------------
__device__ __forceinline__ float gelu_exact(float x){
    return 0.5f * x * (1.0f + erff(x * 0.70710678118654752440f));
}

__device__ __forceinline__ uint32_t rotl32(uint32_t x, int r){
    return (x << r) | (x >> (32 - r));
}

// Distance computed exactly as XLA lowers jnp.sum((a-b)**2, -1):
// un-fused sub/mul, left-to-right add (discrete decisions depend on this).
__device__ __forceinline__ float d2_exact(float ax, float ay, float az,
                                          float bx, float by, float bz){
    float dx = __fsub_rn(ax, bx);
    float dy = __fsub_rn(ay, by);
    float dz = __fsub_rn(az, bz);
    float sx = __fmul_rn(dx, dx);
    float sy = __fmul_rn(dy, dy);
    float sz = __fmul_rn(dz, dz);
    return __fadd_rn(__fadd_rn(sx, sy), sz);
}

// JAX *partitionable* threefry (default since jax 0.4.36), key = (0, 42).
// counter = (0, i), output = x0_final ^ x1_final.
__device__ __forceinline__ uint32_t threefry_bits(uint32_t i){
    const uint32_t k0 = 0u, k1 = 42u;
    const uint32_t k2 = 0x1BD11BDAu ^ k0 ^ k1;
    uint32_t x0 = 0u + k0;
    uint32_t x1 = i  + k1;
#define TFR(r) { x0 += x1; x1 = rotl32(x1, r); x1 ^= x0; }
    TFR(13) TFR(15) TFR(26) TFR(6)
    x0 += k1; x1 += k2 + 1u;
    TFR(17) TFR(29) TFR(16) TFR(24)
    x0 += k2; x1 += k0 + 2u;
    TFR(13) TFR(15) TFR(26) TFR(6)
    x0 += k0; x1 += k1 + 3u;
    TFR(17) TFR(29) TFR(16) TFR(24)
    x0 += k1; x1 += k2 + 4u;
    TFR(13) TFR(15) TFR(26) TFR(6)
    x0 += k2; x1 += k0 + 5u;
#undef TFR
    return x0 ^ x1;
}

__device__ __forceinline__ float gumbel_at(uint32_t i){
    uint32_t bits = threefry_bits(i);
    float u = __uint_as_float((bits >> 9) | 0x3F800000u) - 1.0f;   // [0,1)
    float r = __fadd_rn(u, 1e-9f);
    r = fmaxf(1e-9f, r);
    return -logf(-logf(r));
}

// ---------------- init ------------------------------------------------------
__global__ void k_init(){
    int t = threadIdx.x;
    if (t < BB) { g_bsum[t] = 0.0; g_bsq[t] = 0.0; }
    if (t < H1C){ g_s1[t] = 0.0;  g_q1[t] = 0.0; }
    if (t < H2C){ g_s2[t] = 0.0;  g_q2[t] = 0.0; }
}

// ---------------- weight repack ---------------------------------------------
__global__ void k_prep(const float* __restrict__ mixw, const float* __restrict__ m1w2,
                       const float* __restrict__ m2w1, const float* __restrict__ m2w2,
                       const float* __restrict__ resw){
    int i = blockIdx.x * blockDim.x + threadIdx.x;   // up to 16384
    if (i < 134*64)  g_mixwt[i] = mixw[(i & 63) * 134 + (i >> 6)];
    if (i < 64*64)   g_m1w2t[i] = m1w2[(i & 63) * 64  + (i >> 6)];
    if (i < 64*128){
        int cc = i >> 7, r = i & 127, c = r >> 1, h = r & 1;
        g_m2w1p[i] = m2w1[(c + 64*h)*64 + cc];
    }
    if (i < 128*128) g_m2w2t[i] = m2w2[(i & 127) * 128 + (i >> 7)];
    if (i < 64*128)  g_reswt[i] = resw[(i & 127) * 64 + (i >> 7)];
}

// ---------------- farthest point sampling -----------------------------------
__global__ void k_fps(const float* __restrict__ xyz, float* __restrict__ out_nx){
    int b = blockIdx.x;
    const float* X = xyz + (size_t)b * NN * 3;
    int t = threadIdx.x;
    int lane = t & 31, warp = t >> 5;

    float px[4], py[4], pz[4], mind[4];
    const float FINF = __int_as_float(0x7f800000);
#pragma unroll
    for (int k = 0; k < 4; k++){
        int j = t + k * 1024;
        px[k] = X[j*3]; py[k] = X[j*3+1]; pz[k] = X[j*3+2];
        mind[k] = FINF;
    }
    __shared__ float s_v[32];
    __shared__ int   s_i[32];
    __shared__ int   s_last;

    if (t == 0){
        g_new_idx[b*SS] = 0;
        out_nx[(size_t)(b*SS)*3+0] = X[0];
        out_nx[(size_t)(b*SS)*3+1] = X[1];
        out_nx[(size_t)(b*SS)*3+2] = X[2];
    }
    int last = 0;
    for (int it = 1; it < SS; ++it){
        float qx = X[last*3], qy = X[last*3+1], qz = X[last*3+2];
        float bv = -1.0f; int bi = 0x7fffffff;
#pragma unroll
        for (int k = 0; k < 4; k++){
            float d = d2_exact(px[k], py[k], pz[k], qx, qy, qz);
            float m = fminf(mind[k], d);
            mind[k] = m;
            int j = t + k * 1024;
            if (m > bv || (m == bv && j < bi)) { bv = m; bi = j; }
        }
#pragma unroll
        for (int off = 16; off > 0; off >>= 1){
            float ov = __shfl_down_sync(0xffffffffu, bv, off);
            int   oi = __shfl_down_sync(0xffffffffu, bi, off);
            if (ov > bv || (ov == bv && oi < bi)) { bv = ov; bi = oi; }
        }
        if (lane == 0){ s_v[warp] = bv; s_i[warp] = bi; }
        __syncthreads();
        if (warp == 0){
            bv = s_v[lane]; bi = s_i[lane];
#pragma unroll
            for (int off = 16; off > 0; off >>= 1){
                float ov = __shfl_down_sync(0xffffffffu, bv, off);
                int   oi = __shfl_down_sync(0xffffffffu, bi, off);
                if (ov > bv || (ov == bv && oi < bi)) { bv = ov; bi = oi; }
            }
            if (lane == 0){
                s_last = bi;
                g_new_idx[b*SS + it] = bi;
                out_nx[(size_t)(b*SS+it)*3+0] = X[bi*3];
                out_nx[(size_t)(b*SS+it)*3+1] = X[bi*3+1];
                out_nx[(size_t)(b*SS+it)*3+2] = X[bi*3+2];
            }
        }
        __syncthreads();
        last = s_last;
    }
}

// ---------------- ball query ------------------------------------------------
__global__ void k_ballq(const float* __restrict__ xyz, const float* __restrict__ nx){
    extern __shared__ float sx[];   // NN*3 floats = 48 KB
    int b = blockIdx.x >> 7;
    int t = threadIdx.x;
    int warp = t >> 5, lane = t & 31;
    const float* X = xyz + (size_t)b * NN * 3;
    for (int i = t; i < NN*3; i += 256) sx[i] = X[i];
    __syncthreads();

    int s = ((blockIdx.x & 127) << 3) + warp;
    int bs = b * SS + s;
    float cx = nx[(size_t)bs*3], cy = nx[(size_t)bs*3+1], cz = nx[(size_t)bs*3+2];
    const float r2 = 0.04f;
    int cnt = 0;
    int* G = g_gidx + (size_t)bs * NSK;
    for (int base = 0; base < NN; base += 32){
        int j = base + lane;
        float d2 = d2_exact(cx, cy, cz, sx[j*3], sx[j*3+1], sx[j*3+2]);
        bool w = d2 < r2;
        unsigned m = __ballot_sync(0xffffffffu, w);
        int off = __popc(m & ((1u << lane) - 1u));
        if (w && (cnt + off) < NSK) G[cnt + off] = j;
        cnt += __popc(m);
        if (cnt >= NSK) break;
    }
    if (cnt < NSK){
        for (int q = cnt + lane; q < NSK; q += 32) G[q] = -1;
    }
}

// ---------------- per-batch std of gf ----------------------------------------
__global__ void k_std(const float* __restrict__ xyz, const float* __restrict__ f,
                      const float* __restrict__ nx){
    int t = threadIdx.x;
    int row = blockIdx.x * 256 + t;        // 0 .. 262143
    int b  = row >> 15;
    int bs = row >> 5;
    int gi = g_gidx[row];
    int si = g_new_idx[bs];
    const float* Fs = f + ((size_t)b*NN + si) * CINC;
    float cx = nx[(size_t)bs*3], cy = nx[(size_t)bs*3+1], cz = nx[(size_t)bs*3+2];
    float gx = 0.f, gy = 0.f, gz = 0.f;
    const float* Fg = f;
    if (gi >= 0){
        const float* P = xyz + ((size_t)b*NN + gi)*3;
        gx = P[0]; gy = P[1]; gz = P[2];
        Fg = f + ((size_t)b*NN + gi) * CINC;
    }
    double ls = 0.0, lq = 0.0;
    float v;
    v = gx;      ls += v; lq += (double)v*v;
    v = gy;      ls += v; lq += (double)v*v;
    v = gz;      ls += v; lq += (double)v*v;
    v = gx - cx; ls += v; lq += (double)v*v;
    v = gy - cy; ls += v; lq += (double)v*v;
    v = gz - cz; ls += v; lq += (double)v*v;
    for (int c = 0; c < CINC; c++){
        float fv = (gi >= 0) ? Fg[c] : 0.0f;
        v = fv - Fs[c]; ls += v; lq += (double)v*v;
    }
    __shared__ double sd[256];
    sd[t] = ls; __syncthreads();
    for (int o = 128; o > 0; o >>= 1){ if (t < o) sd[t] += sd[t+o]; __syncthreads(); }
    if (t == 0) atomicAdd(&g_bsum[b], sd[0]);
    __syncthreads();
    sd[t] = lq; __syncthreads();
    for (int o = 128; o > 0; o >>= 1){ if (t < o) sd[t] += sd[t+o]; __syncthreads(); }
    if (t == 0) atomicAdd(&g_bsq[b], sd[0]);
}

__global__ void k_stdfin(){
    int b = threadIdx.x;
    if (b < BB){
        double cnt = (double)SS * NSK * (CINC + 6);
        double s = g_bsum[b], q = g_bsq[b];
        double mean = s / cnt;
        double var = (q - s * mean) / (cnt - 1.0);
        g_std[b] = (float)sqrt(var);
    }
}

// ---------------- grouped_f (= group_skip), 4 neighbors per weight pass ------
__global__ void k_groupedf(const float* __restrict__ xyz, const float* __restrict__ f,
                           const float* __restrict__ aw, const float* __restrict__ ab,
                           const float* __restrict__ mixb, const float* __restrict__ nx){
    __shared__ float s_w[134*64];
    __shared__ __align__(16) float s_gf[134*4];      // [cc][q]
    __shared__ float s_samp[CINC];
    __shared__ float s_aw[70], s_ab[70];
    int bs = blockIdx.x; int b = bs >> 10;
    int t = threadIdx.x;   // 64
    for (int i = t; i < 134*64; i += 64) s_w[i] = g_mixwt[i];
    int si = g_new_idx[bs];
    s_samp[t] = f[((size_t)b*NN + si)*CINC + t];
    for (int i = t; i < 70; i += 64){ s_aw[i] = aw[i]; s_ab[i] = ab[i]; }
    float cx = nx[(size_t)bs*3], cy = nx[(size_t)bs*3+1], cz = nx[(size_t)bs*3+2];
    float stdp = g_std[b] + 1e-5f;
    float mb = mixb[t];
    __syncthreads();
    for (int it = 0; it < 8; it++){
        int row0 = bs * NSK + it*4;
        // build gf for 4 neighbors, interleaved [cc][q]
#pragma unroll
        for (int q = 0; q < 4; q++){
            int gi = g_gidx[row0 + q];
            for (int c = t; c < 134; c += 64){
                float val;
                if (c < 70){
                    float raw;
                    if (c < 3){
                        raw = (gi >= 0) ? xyz[((size_t)b*NN+gi)*3 + c] : 0.0f;
                    } else if (c < 6){
                        float g = (gi >= 0) ? xyz[((size_t)b*NN+gi)*3 + (c-3)] : 0.0f;
                        float cen = (c == 3) ? cx : (c == 4) ? cy : cz;
                        raw = g - cen;
                    } else {
                        float g = (gi >= 0) ? f[((size_t)b*NN+gi)*CINC + (c-6)] : 0.0f;
                        raw = g - s_samp[c-6];
                    }
                    val = (raw / stdp) * s_aw[c] + s_ab[c];
                } else {
                    val = s_samp[c-70];
                }
                s_gf[c*4 + q] = val;
            }
        }
        __syncthreads();
        float a0 = mb, a1 = mb, a2 = mb, a3 = mb;
#pragma unroll 2
        for (int c = 0; c < 134; c++){
            float w = s_w[c*64 + t];
            float4 g4 = *(const float4*)&s_gf[c*4];
            a0 += g4.x * w; a1 += g4.y * w; a2 += g4.z * w; a3 += g4.w * w;
        }
        g_skip[(size_t)(row0+0)*CINC + t] = a0;
        g_skip[(size_t)(row0+1)*CINC + t] = a1;
        g_skip[(size_t)(row0+2)*CINC + t] = a2;
        g_skip[(size_t)(row0+3)*CINC + t] = a3;
        __syncthreads();
    }
}

// ---------------- BN1 statistics (recompute h) -------------------------------
__global__ void k_bn1(const float* __restrict__ xyz, const int* __restrict__ cidx,
                      const float* __restrict__ w1, const float* __restrict__ b1){
    int t = threadIdx.x;   // 64 = channel
    int row0 = blockIdx.x * 256;
    int b = row0 >> 15;
    __shared__ float s_mc[12];
    if (t < 12){
        int v = t / 3, k = t % 3;
        s_mc[t] = xyz[((size_t)b*NN + cidx[v])*3 + k];
    }
    float w[13];
#pragma unroll
    for (int c = 0; c < 13; c++) w[c] = w1[t*13 + c];
    float bb = b1[t];
    __syncthreads();
    double ls = 0.0, lq = 0.0;
    for (int r = 0; r < 256; r++){
        int row = row0 + r;
        int gi = g_gidx[row];
        float gx = 0.f, gy = 0.f, gz = 0.f;
        if (gi >= 0){
            const float* P = xyz + ((size_t)b*NN + gi)*3;
            gx = P[0]; gy = P[1]; gz = P[2];
        }
#pragma unroll
        for (int v = 0; v < VV; v++){
            float mx = s_mc[v*3], my = s_mc[v*3+1], mz = s_mc[v*3+2];
            float ax = gx - mx, ay = gy - my, az = gz - mz;
            float eu = sqrtf(ax*ax + ay*ay + az*az);
            float h = bb - w[0]*ax - w[1]*ay - w[2]*az
                         + w[3]*ax + w[4]*ay + w[5]*az
                         + w[6]*eu + w[7]*gx + w[8]*gy + w[9]*gz
                         + w[10]*mx + w[11]*my + w[12]*mz;
            ls += h; lq += (double)h*h;
        }
    }
    atomicAdd(&g_s1[t], ls);
    atomicAdd(&g_q1[t], lq);
}

__global__ void k_bn1fin(const float* __restrict__ g1, const float* __restrict__ be1){
    int t = threadIdx.x;
    if (t < H1C){
        double cnt = (double)BB * SS * NSK * VV;
        double mean = g_s1[t] / cnt;
        double var  = g_q1[t] / cnt - mean * mean;
        float sc = g1[t] / sqrtf((float)var + 1e-5f);
        g_sc1[t] = sc;
        g_sh1[t] = be1[t] - (float)mean * sc;
    }
}

// ---------------- main fused kernel: 256 thr = 4 n-slots x 64 channels -------
__global__ void __launch_bounds__(256)
k_main(const float* __restrict__ xyz, const int* __restrict__ cidx,
       const float* __restrict__ w1, const float* __restrict__ b1,
       const float* __restrict__ m1b2, const float* __restrict__ m2b1){
    extern __shared__ __align__(16) float sm[];
    float*  s_w2   = sm;                 // 4096  : m1_w2^T  [cc][o]
    float*  s_mw1  = sm + 4096;          // 8192  : m2_w1 paired [cc][c][2]
    float*  s_h    = sm + 12288;         // 1024  : [q][cc][v]
    float*  s_agg  = sm + 13312;         // 256   : [q][c]
    double* s_stat = (double*)(sm + 13568); // 256 doubles (512 floats)
    float*  s_mc   = sm + 14080;         // 12

    int bs = blockIdx.x; int b = bs >> 10;
    int t  = threadIdx.x;
    int q  = t >> 6, tc = t & 63;

    for (int i = t; i < 4096; i += 256) s_w2[i]  = g_m1w2t[i];
    for (int i = t; i < 8192; i += 256) s_mw1[i] = g_m2w1p[i];
    if (t < 12){ int v = t/3, k = t%3; s_mc[t] = xyz[((size_t)b*NN + cidx[v])*3 + k]; }
    s_stat[t] = 0.0;
    float w[13];
#pragma unroll
    for (int c = 0; c < 13; c++) w[c] = w1[tc*13 + c];
    float bb = b1[tc], sc1 = g_sc1[tc], sh1 = g_sh1[tc], b2 = m1b2[tc];
    float mb1a = m2b1[tc], mb1b = m2b1[tc + 64];
    double s2a = 0, q2a = 0, s2b = 0, q2b = 0;
    __syncthreads();

    for (int it = 0; it < 8; it++){
        int n = it*4 + q;
        int row = bs * NSK + n;
        int gi = g_gidx[row];
        float gx = 0.f, gy = 0.f, gz = 0.f;
        if (gi >= 0){
            const float* P = xyz + ((size_t)b*NN + gi)*3;
            gx = P[0]; gy = P[1]; gz = P[2];
        }
        float hv[VV];
#pragma unroll
        for (int v = 0; v < VV; v++){
            float mx = s_mc[v*3], my = s_mc[v*3+1], mz = s_mc[v*3+2];
            float ax = gx - mx, ay = gy - my, az = gz - mz;
            float eu = sqrtf(ax*ax + ay*ay + az*az);
            float h = bb - w[0]*ax - w[1]*ay - w[2]*az
                         + w[3]*ax + w[4]*ay + w[5]*az
                         + w[6]*eu + w[7]*gx + w[8]*gy + w[9]*gz
                         + w[10]*mx + w[11]*my + w[12]*mz;
            h = h * sc1 + sh1;
            hv[v] = gelu_exact(h);
        }
        *(float4*)&s_h[q*256 + tc*4] = make_float4(hv[0], hv[1], hv[2], hv[3]);
        __syncthreads();

        float skip = g_skip[(size_t)row*CINC + tc];
        float acc0 = b2, acc1 = b2, acc2 = b2, acc3 = b2;
#pragma unroll 4
        for (int cc = 0; cc < 64; cc++){
            float ww = s_w2[cc*64 + tc];
            float4 h4 = *(const float4*)&s_h[q*256 + cc*4];
            acc0 += h4.x * ww; acc1 += h4.y * ww;
            acc2 += h4.z * ww; acc3 += h4.w * ww;
        }
        float lo[VV] = {skip*acc0, skip*acc1, skip*acc2, skip*acc3};
        float zz[VV];
        uint32_t fibase = ((uint32_t)row * 4u) * 64u + (uint32_t)tc;
#pragma unroll
        for (int v = 0; v < VV; v++)
            zz[v] = lo[v] + gumbel_at(fibase + (uint32_t)v * 64u);
        float m = fmaxf(fmaxf(zz[0], zz[1]), fmaxf(zz[2], zz[3]));
        float se = 0.f, sl = 0.f;
#pragma unroll
        for (int v = 0; v < VV; v++){
            float e = expf(zz[v] - m);
            se += e; sl += e * lo[v];
        }
        float agg = sl / se + skip;
        if (gi < 0) agg = 0.0f;
        s_agg[q*64 + tc] = agg;
        __syncthreads();

        float ha = mb1a, hb = mb1b;
#pragma unroll 4
        for (int cc4 = 0; cc4 < 64; cc4 += 4){
            float4 a4 = *(const float4*)&s_agg[q*64 + cc4];
            float2 w0 = *(const float2*)&s_mw1[(cc4+0)*128 + 2*tc];
            float2 w1p= *(const float2*)&s_mw1[(cc4+1)*128 + 2*tc];
            float2 w2p= *(const float2*)&s_mw1[(cc4+2)*128 + 2*tc];
            float2 w3p= *(const float2*)&s_mw1[(cc4+3)*128 + 2*tc];
            ha += a4.x*w0.x; hb += a4.x*w0.y;
            ha += a4.y*w1p.x; hb += a4.y*w1p.y;
            ha += a4.z*w2p.x; hb += a4.z*w2p.y;
            ha += a4.w*w3p.x; hb += a4.w*w3p.y;
        }
        g_h2v[(size_t)row*H2C + tc]      = ha;
        g_h2v[(size_t)row*H2C + tc + 64] = hb;
        s2a += ha; q2a += (double)ha*ha;
        s2b += hb; q2b += (double)hb*hb;
        __syncthreads();
    }
    // reduce the 4 q-slots in smem before global atomics
    atomicAdd(&s_stat[tc],       s2a);
    atomicAdd(&s_stat[64 + tc],  q2a);
    atomicAdd(&s_stat[128 + tc], s2b);
    atomicAdd(&s_stat[192 + tc], q2b);
    __syncthreads();
    if (q == 0){
        atomicAdd(&g_s2[tc],      s_stat[tc]);
        atomicAdd(&g_q2[tc],      s_stat[64 + tc]);
        atomicAdd(&g_s2[tc + 64], s_stat[128 + tc]);
        atomicAdd(&g_q2[tc + 64], s_stat[192 + tc]);
    }
}

__global__ void k_bn2fin(const float* __restrict__ g2, const float* __restrict__ be2){
    int t = threadIdx.x;
    if (t < H2C){
        double cnt = (double)BB * SS * NSK;
        double mean = g_s2[t] / cnt;
        double var  = g_q2[t] / cnt - mean * mean;
        float sc = g2[t] / sqrtf((float)var + 1e-5f);
        g_sc2[t] = sc;
        g_sh2[t] = be2[t] - (float)mean * sc;
    }
}

// ---------------- final kernel: 8 neighbors per weight pass -------------------
__global__ void __launch_bounds__(128)
k_final(const float* __restrict__ m2b2, const float* __restrict__ resb,
        float* __restrict__ out_f){
    extern __shared__ __align__(16) float sm[];
    float* s_w = sm;            // 16384 : m2_w2^T [cc][o]
    float* s_r = sm + 16384;    // 8192  : res_w^T [cc][o]
    float* s_h = sm + 24576;    // 1024  : [q][128]
    float* s_k = sm + 25600;    // 512   : [q][64]
    int bs = blockIdx.x;
    int t = threadIdx.x;   // 128
    for (int i = t; i < 16384; i += 128) s_w[i] = g_m2w2t[i];
    for (int i = t; i < 8192;  i += 128) s_r[i] = g_reswt[i];
    float obrb = m2b2[t] + resb[t];
    float sc2 = g_sc2[t], sh2 = g_sh2[t];
    __syncthreads();
    float mx = -3.4e38f;
    for (int it = 0; it < 4; it++){
        int row0 = bs * NSK + it*8;
#pragma unroll
        for (int qq = 0; qq < 8; qq++){
            s_h[qq*128 + t] = g_h2v[(size_t)(row0+qq)*H2C + t] * sc2 + sh2;
            if (t < 64) s_k[qq*64 + t] = g_skip[(size_t)(row0+qq)*CINC + t];
        }
        __syncthreads();
        float acc[8];
#pragma unroll
        for (int qq = 0; qq < 8; qq++) acc[qq] = obrb;
#pragma unroll 2
        for (int cc = 0; cc < 128; cc += 4){
            float w0 = s_w[(cc+0)*128 + t];
            float w1 = s_w[(cc+1)*128 + t];
            float w2 = s_w[(cc+2)*128 + t];
            float w3 = s_w[(cc+3)*128 + t];
#pragma unroll
            for (int qq = 0; qq < 8; qq++){
                float4 h4 = *(const float4*)&s_h[qq*128 + cc];
                acc[qq] += h4.x*w0 + h4.y*w1 + h4.z*w2 + h4.w*w3;
            }
        }
#pragma unroll 2
        for (int cc = 0; cc < 64; cc += 4){
            float r0 = s_r[(cc+0)*128 + t];
            float r1 = s_r[(cc+1)*128 + t];
            float r2 = s_r[(cc+2)*128 + t];
            float r3 = s_r[(cc+3)*128 + t];
#pragma unroll
            for (int qq = 0; qq < 8; qq++){
                float4 k4 = *(const float4*)&s_k[qq*64 + cc];
                acc[qq] += k4.x*r0 + k4.y*r1 + k4.z*r2 + k4.w*r3;
            }
        }
#pragma unroll
        for (int qq = 0; qq < 8; qq++)
            mx = fmaxf(mx, gelu_exact(acc[qq]));
        __syncthreads();
    }
    out_f[(size_t)bs*COUTC + t] = mx;
}

// ---------------- launch -----------------------------------------------------
extern "C" void kernel_launch(void* const* d_in, const int* in_sizes, int n_in,
                              void* d_out, int out_size){
    const float* xyz   = (const float*)d_in[0];
    const float* f     = (const float*)d_in[1];
    const int*   cidx  = (const int*)  d_in[2];
    const float* aw    = (const float*)d_in[3];
    const float* ab    = (const float*)d_in[4];
    const float* mixw  = (const float*)d_in[5];
    const float* mixb  = (const float*)d_in[6];
    const float* m1w1  = (const float*)d_in[7];
    const float* m1b1  = (const float*)d_in[8];
    const float* m1g1  = (const float*)d_in[9];
    const float* m1be1 = (const float*)d_in[10];
    const float* m1w2  = (const float*)d_in[11];
    const float* m1b2  = (const float*)d_in[12];
    const float* m2w1  = (const float*)d_in[13];
    const float* m2b1  = (const float*)d_in[14];
    const float* m2g1  = (const float*)d_in[15];
    const float* m2be1 = (const float*)d_in[16];
    const float* m2w2  = (const float*)d_in[17];
    const float* m2b2  = (const float*)d_in[18];
    const float* resw  = (const float*)d_in[19];
    const float* resb  = (const float*)d_in[20];
    (void)in_sizes; (void)n_in; (void)out_size;

    float* outf = (float*)d_out;                       // (B,S,COUT)
    float* outx = outf + (size_t)BB*SS*COUTC;          // (B,S,3)

    cudaFuncSetAttribute(k_ballq, cudaFuncAttributeMaxDynamicSharedMemorySize, 49152);
    cudaFuncSetAttribute(k_main,  cudaFuncAttributeMaxDynamicSharedMemorySize, 57344);
    cudaFuncSetAttribute(k_final, cudaFuncAttributeMaxDynamicSharedMemorySize, 106496);

    k_init<<<1, 256>>>();
    k_prep<<<64, 256>>>(mixw, m1w2, m2w1, m2w2, resw);
    k_fps<<<BB, 1024>>>(xyz, outx);
    k_ballq<<<BB*SS/8, 256, 49152>>>(xyz, outx);
    k_std<<<(BB*SS*NSK)/256, 256>>>(xyz, f, outx);
    k_stdfin<<<1, 32>>>();
    k_groupedf<<<BB*SS, 64>>>(xyz, f, aw, ab, mixb, outx);
    k_bn1<<<1024, 64>>>(xyz, cidx, m1w1, m1b1);
    k_bn1fin<<<1, 64>>>(m1g1, m1be1);
    k_main<<<BB*SS, 256, 56384>>>(xyz, cidx, m1w1, m1b1, m1b2, m2b1);
    k_bn2fin<<<1, 128>>>(m2g1, m2be1);
    k_final<<<BB*SS, 128, 104448>>>(m2b2, resb, outf);
}